// round 3
// baseline (speedup 1.0000x reference)
#include <cuda_runtime.h>
#include <cstdint>
#include <cstdio>

// Problem constants
#define B_    4
#define NPM_  200
#define NVM_  1500
#define D_    512
#define H_    8
#define DFF_  2048
#define NL_   3
#define S_    1702           // NPM + NVM + 2
#define M_    (B_ * S_)      // 6808 rows
#define DH_   64
#define RELW_ (NPM_ + NVM_)  // 1700

// ----------------------------------------------------------------------------
// Scratch (static device globals; no allocation allowed)
// ----------------------------------------------------------------------------
__device__ float g_x  [M_ * D_];        // residual stream
__device__ float g_h  [M_ * D_];        // layernorm output
__device__ float g_qkv[M_ * 3 * D_];    // qkv projection
__device__ float g_o  [M_ * D_];        // attention output
__device__ float g_ff [M_ * DFF_];      // ffn hidden

// ----------------------------------------------------------------------------
// build_x: x[b,0,:]=num_step; x[b,1..200]=pm_enc; x[b,201..1700]=vm_enc; x[b,-1]=-1
// ----------------------------------------------------------------------------
__global__ void build_x_kernel(const float* __restrict__ vm,
                               const float* __restrict__ ns,
                               const float* __restrict__ pm,
                               const float* __restrict__ pmW, const float* __restrict__ pmb,
                               const float* __restrict__ vmW, const float* __restrict__ vmb,
                               float* __restrict__ x)
{
    int idx = blockIdx.x * blockDim.x + threadIdx.x;
    if (idx >= M_ * D_) return;
    int d = idx & (D_ - 1);
    int sb = idx >> 9;          // /512
    int s = sb % S_;
    int b = sb / S_;
    float val;
    if (s == 0) {
        val = ns[b];
    } else if (s <= NPM_) {
        const float* st = pm + ((size_t)b * NPM_ + (s - 1)) * 16;
        val = pmb[d];
        #pragma unroll
        for (int c = 0; c < 16; c++) val += st[c] * pmW[c * D_ + d];
    } else if (s < S_ - 1) {
        const float* st = vm + ((size_t)b * NVM_ + (s - 1 - NPM_)) * 16;
        val = vmb[d];
        #pragma unroll
        for (int c = 0; c < 16; c++) val += st[c] * vmW[c * D_ + d];
    } else {
        val = -1.0f;
    }
    x[idx] = val;
}

// ----------------------------------------------------------------------------
// LayerNorm: one warp per row of 512
// ----------------------------------------------------------------------------
__global__ void ln_kernel(const float* __restrict__ x, float* __restrict__ out,
                          const float* __restrict__ gs, const float* __restrict__ gb,
                          int M)
{
    int warp = (blockIdx.x * blockDim.x + threadIdx.x) >> 5;
    int lane = threadIdx.x & 31;
    if (warp >= M) return;
    const float* row = x + (size_t)warp * D_;
    float4 v[4];
    float sum = 0.f, sq = 0.f;
    #pragma unroll
    for (int j = 0; j < 4; j++) {
        v[j] = *reinterpret_cast<const float4*>(row + (lane + 32 * j) * 4);
        sum += v[j].x + v[j].y + v[j].z + v[j].w;
        sq  += v[j].x * v[j].x + v[j].y * v[j].y + v[j].z * v[j].z + v[j].w * v[j].w;
    }
    #pragma unroll
    for (int o = 16; o; o >>= 1) {
        sum += __shfl_xor_sync(0xffffffffu, sum, o);
        sq  += __shfl_xor_sync(0xffffffffu, sq,  o);
    }
    const float inv = 1.0f / (float)D_;
    float mean = sum * inv;
    float var  = sq * inv - mean * mean;
    float rstd = rsqrtf(var + 1e-5f);
    float* orow = out + (size_t)warp * D_;
    #pragma unroll
    for (int j = 0; j < 4; j++) {
        int c = (lane + 32 * j) * 4;
        float4 r;
        r.x = (v[j].x - mean) * rstd * gs[c + 0] + gb[c + 0];
        r.y = (v[j].y - mean) * rstd * gs[c + 1] + gb[c + 1];
        r.z = (v[j].z - mean) * rstd * gs[c + 2] + gb[c + 2];
        r.w = (v[j].w - mean) * rstd * gs[c + 3] + gb[c + 3];
        *reinterpret_cast<float4*>(orow + c) = r;
    }
}

// ----------------------------------------------------------------------------
// SGEMM: C[M,N] = epi(A[M,K] @ W[K,N] + bias)
//   EPI 0: store   EPI 1: C += (residual)   EPI 2: exact GELU
// 64x64 tile, BK=16, 256 threads, 4x4 per-thread micro-tile.
// N must be multiple of 64, K multiple of 16.
// ----------------------------------------------------------------------------
template<int EPI>
__global__ void sgemm_kernel(const float* __restrict__ A, const float* __restrict__ W,
                             const float* __restrict__ bias, float* __restrict__ C,
                             int M, int N, int K)
{
    __shared__ float As[16][64];
    __shared__ float Ws[16][64];
    int tid = threadIdx.x;
    int ty = tid >> 4, tx = tid & 15;
    int row0 = blockIdx.y * 64;
    int col0 = blockIdx.x * 64;

    float acc[4][4];
    #pragma unroll
    for (int i = 0; i < 4; i++)
        #pragma unroll
        for (int j = 0; j < 4; j++) acc[i][j] = 0.f;

    int arow = tid >> 2;          // 0..63
    int aseg = (tid & 3) * 4;     // 0,4,8,12
    int wrow = tid >> 4;          // 0..15
    int wcol = (tid & 15) * 4;

    for (int k0 = 0; k0 < K; k0 += 16) {
        int m = row0 + arow;
        float4 av = make_float4(0.f, 0.f, 0.f, 0.f);
        if (m < M) av = *reinterpret_cast<const float4*>(A + (size_t)m * K + k0 + aseg);
        As[aseg + 0][arow] = av.x;
        As[aseg + 1][arow] = av.y;
        As[aseg + 2][arow] = av.z;
        As[aseg + 3][arow] = av.w;
        float4 wv = *reinterpret_cast<const float4*>(W + (size_t)(k0 + wrow) * N + col0 + wcol);
        *reinterpret_cast<float4*>(&Ws[wrow][wcol]) = wv;
        __syncthreads();
        #pragma unroll
        for (int kk = 0; kk < 16; kk++) {
            float a[4], b[4];
            #pragma unroll
            for (int i = 0; i < 4; i++) a[i] = As[kk][ty + 16 * i];
            #pragma unroll
            for (int j = 0; j < 4; j++) b[j] = Ws[kk][tx + 16 * j];
            #pragma unroll
            for (int i = 0; i < 4; i++)
                #pragma unroll
                for (int j = 0; j < 4; j++) acc[i][j] += a[i] * b[j];
        }
        __syncthreads();
    }

    #pragma unroll
    for (int i = 0; i < 4; i++) {
        int m = row0 + ty + 16 * i;
        if (m >= M) continue;
        #pragma unroll
        for (int j = 0; j < 4; j++) {
            int n = col0 + tx + 16 * j;
            float v = acc[i][j] + bias[n];
            float* p = C + (size_t)m * N + n;
            if (EPI == 0) {
                *p = v;
            } else if (EPI == 1) {
                *p += v;
            } else {
                *p = 0.5f * v * (1.0f + erff(v * 0.70710678118654752f));
            }
        }
    }
}

// ----------------------------------------------------------------------------
// Flash attention: one block handles 64 queries for one (b,h).
// qkv layout: [B*S][1536], q at h*64, k at 512+h*64, v at 1024+h*64.
// mask(q,k) = (q,k inner && rel[q-1]!=rel[k-1]) || (k in vm-range && pad[k])
// ----------------------------------------------------------------------------
__global__ void flash_kernel(const float* __restrict__ qkv,
                             const int* __restrict__ rel,
                             const unsigned char* __restrict__ padm,
                             float* __restrict__ obuf)
{
    extern __shared__ float smem[];
    float (*Qs)[65] = (float(*)[65])(smem);
    float (*Ks)[65] = (float(*)[65])(smem + 64 * 65);
    float (*Vs)[65] = (float(*)[65])(smem + 2 * 64 * 65);
    float (*Ps)[65] = (float(*)[65])(smem + 3 * 64 * 65);
    int* relq_s = (int*)(smem + 4 * 64 * 65);
    int* relk_s = relq_s + 64;
    int* padk_s = relk_s + 64;

    int tid = threadIdx.x;
    int ty = tid >> 4, tx = tid & 15;
    int bh = blockIdx.y;
    int b = bh / H_, h = bh % H_;
    int qt = blockIdx.x * 64;
    const size_t rs = 3 * D_;  // 1536
    const float* qbase = qkv + (size_t)b * S_ * rs + h * DH_;
    const float* kbase = qbase + D_;
    const float* vbase = qbase + 2 * D_;

    // Load Q tile
    #pragma unroll
    for (int l = 0; l < 4; l++) {
        int idx = tid + l * 256;
        int r = idx >> 4, c4 = (idx & 15) * 4;
        int q = qt + r;
        float4 v = make_float4(0.f, 0.f, 0.f, 0.f);
        if (q < S_) v = *reinterpret_cast<const float4*>(qbase + (size_t)q * rs + c4);
        Qs[r][c4 + 0] = v.x; Qs[r][c4 + 1] = v.y; Qs[r][c4 + 2] = v.z; Qs[r][c4 + 3] = v.w;
    }
    if (tid < 64) {
        int q = qt + tid;
        relq_s[tid] = (q >= 1 && q < S_ - 1) ? rel[b * RELW_ + q - 1] : -1;
    }
    __syncthreads();

    float m_i[4], l_i[4], o_acc[4][4];
    #pragma unroll
    for (int i = 0; i < 4; i++) {
        m_i[i] = -1e30f; l_i[i] = 0.f;
        #pragma unroll
        for (int j = 0; j < 4; j++) o_acc[i][j] = 0.f;
    }

    for (int kt = 0; kt < S_; kt += 64) {
        // Load K,V tiles + metadata
        #pragma unroll
        for (int l = 0; l < 4; l++) {
            int idx = tid + l * 256;
            int r = idx >> 4, c4 = (idx & 15) * 4;
            int k = kt + r;
            float4 kv = make_float4(0.f, 0.f, 0.f, 0.f);
            float4 vv = make_float4(0.f, 0.f, 0.f, 0.f);
            if (k < S_) {
                kv = *reinterpret_cast<const float4*>(kbase + (size_t)k * rs + c4);
                vv = *reinterpret_cast<const float4*>(vbase + (size_t)k * rs + c4);
            }
            Ks[r][c4 + 0] = kv.x; Ks[r][c4 + 1] = kv.y; Ks[r][c4 + 2] = kv.z; Ks[r][c4 + 3] = kv.w;
            Vs[r][c4 + 0] = vv.x; Vs[r][c4 + 1] = vv.y; Vs[r][c4 + 2] = vv.z; Vs[r][c4 + 3] = vv.w;
        }
        if (tid < 64) {
            int k = kt + tid;
            relk_s[tid] = (k >= 1 && k < S_ - 1) ? rel[b * RELW_ + k - 1] : -2;
            padk_s[tid] = (k >= 1 + NPM_ && k < S_ - 1) ? (int)padm[b * NVM_ + (k - 1 - NPM_)] : 0;
        }
        __syncthreads();

        // S tile = Q @ K^T
        float sc[4][4];
        #pragma unroll
        for (int i = 0; i < 4; i++)
            #pragma unroll
            for (int j = 0; j < 4; j++) sc[i][j] = 0.f;
        #pragma unroll 8
        for (int d = 0; d < 64; d++) {
            float qv[4], kv[4];
            #pragma unroll
            for (int i = 0; i < 4; i++) qv[i] = Qs[ty + 16 * i][d];
            #pragma unroll
            for (int j = 0; j < 4; j++) kv[j] = Ks[tx + 16 * j][d];
            #pragma unroll
            for (int i = 0; i < 4; i++)
                #pragma unroll
                for (int j = 0; j < 4; j++) sc[i][j] += qv[i] * kv[j];
        }

        // Mask + online softmax
        #pragma unroll
        for (int i = 0; i < 4; i++) {
            int q = qt + ty + 16 * i;
            int rq = relq_s[ty + 16 * i];
            bool innerq = (q >= 1 && q < S_ - 1);
            float rowmax = -1e30f;
            #pragma unroll
            for (int j = 0; j < 4; j++) {
                int c = tx + 16 * j;
                int k = kt + c;
                float val = sc[i][j] * 0.125f;  // DH^-0.5
                bool masked = (innerq && k >= 1 && k < S_ - 1 && rq != relk_s[c]);
                masked = masked || (padk_s[c] != 0);
                if (k >= S_)      val = -1e30f;
                else if (masked)  val = -1e9f;
                sc[i][j] = val;
                rowmax = fmaxf(rowmax, val);
            }
            #pragma unroll
            for (int o = 8; o; o >>= 1)
                rowmax = fmaxf(rowmax, __shfl_xor_sync(0xffffffffu, rowmax, o, 16));
            float mnew = fmaxf(m_i[i], rowmax);
            float corr = __expf(m_i[i] - mnew);
            float rsum = 0.f;
            #pragma unroll
            for (int j = 0; j < 4; j++) {
                float p = __expf(sc[i][j] - mnew);
                sc[i][j] = p;
                rsum += p;
            }
            #pragma unroll
            for (int o = 8; o; o >>= 1)
                rsum += __shfl_xor_sync(0xffffffffu, rsum, o, 16);
            l_i[i] = l_i[i] * corr + rsum;
            #pragma unroll
            for (int j = 0; j < 4; j++) o_acc[i][j] *= corr;
            m_i[i] = mnew;
        }

        // Write P to smem
        #pragma unroll
        for (int i = 0; i < 4; i++)
            #pragma unroll
            for (int j = 0; j < 4; j++) Ps[ty + 16 * i][tx + 16 * j] = sc[i][j];
        __syncthreads();

        // O += P @ V
        #pragma unroll 8
        for (int c = 0; c < 64; c++) {
            float pv[4], vv[4];
            #pragma unroll
            for (int i = 0; i < 4; i++) pv[i] = Ps[ty + 16 * i][c];
            #pragma unroll
            for (int j = 0; j < 4; j++) vv[j] = Vs[c][tx + 16 * j];
            #pragma unroll
            for (int i = 0; i < 4; i++)
                #pragma unroll
                for (int j = 0; j < 4; j++) o_acc[i][j] += pv[i] * vv[j];
        }
        __syncthreads();
    }

    // Normalize + write O
    #pragma unroll
    for (int i = 0; i < 4; i++) {
        int q = qt + ty + 16 * i;
        if (q >= S_) continue;
        float inv = 1.0f / l_i[i];
        float* dst = obuf + ((size_t)b * S_ + q) * D_ + h * DH_;
        #pragma unroll
        for (int j = 0; j < 4; j++) dst[tx + 16 * j] = o_acc[i][j] * inv;
    }
}

// ----------------------------------------------------------------------------
// Output heads: score[b, j] = x[b, 201+j] . out_W + out_b ; critic[b] = x[b,-1] . cr_W + cr_b
// One warp per output element.
// ----------------------------------------------------------------------------
__global__ void out_kernel(const float* __restrict__ x,
                           const float* __restrict__ outW, const float* __restrict__ outb,
                           const float* __restrict__ crW,  const float* __restrict__ crb,
                           float* __restrict__ out)
{
    int warp = (blockIdx.x * blockDim.x + threadIdx.x) >> 5;
    int lane = threadIdx.x & 31;
    const int nscore = B_ * NVM_;
    if (warp >= nscore + B_) return;
    int b, s;
    const float* w;
    float bias;
    float* dst;
    if (warp < nscore) {
        b = warp / NVM_;
        s = 1 + NPM_ + (warp % NVM_);
        w = outW; bias = outb[0];
        dst = out + warp;
    } else {
        b = warp - nscore;
        s = S_ - 1;
        w = crW; bias = crb[0];
        dst = out + nscore + b;
    }
    const float* row = x + ((size_t)b * S_ + s) * D_;
    float sum = 0.f;
    for (int c = lane; c < D_; c += 32) sum += row[c] * w[c];
    #pragma unroll
    for (int o = 16; o; o >>= 1) sum += __shfl_xor_sync(0xffffffffu, sum, o);
    if (lane == 0) *dst = sum + bias;
}

// ----------------------------------------------------------------------------
// Host launcher
// ----------------------------------------------------------------------------
extern "C" void kernel_launch(void* const* d_in, const int* in_sizes, int n_in,
                              void* d_out, int out_size)
{
    const float* vm   = (const float*)d_in[0];
    const float* ns   = (const float*)d_in[1];
    const float* pm   = (const float*)d_in[2];
    const int*   rel  = (const int*)  d_in[3];
    const unsigned char* padm = (const unsigned char*)d_in[4];
    const float* pmW  = (const float*)d_in[5];
    const float* pmb  = (const float*)d_in[6];
    const float* vmW  = (const float*)d_in[7];
    const float* vmb  = (const float*)d_in[8];
    const float* ln1s = (const float*)d_in[9];
    const float* ln1b = (const float*)d_in[10];
    const float* Wqkv = (const float*)d_in[11];
    const float* bqkv = (const float*)d_in[12];
    const float* Wo   = (const float*)d_in[13];
    const float* bo   = (const float*)d_in[14];
    const float* ln2s = (const float*)d_in[15];
    const float* ln2b = (const float*)d_in[16];
    const float* W1   = (const float*)d_in[17];
    const float* b1   = (const float*)d_in[18];
    const float* W2   = (const float*)d_in[19];
    const float* b2   = (const float*)d_in[20];
    const float* outW = (const float*)d_in[21];
    const float* outb = (const float*)d_in[22];
    const float* crW  = (const float*)d_in[23];
    const float* crb  = (const float*)d_in[24];

    float *x, *h, *qkvb, *ob, *ff;
    cudaGetSymbolAddress((void**)&x,    g_x);
    cudaGetSymbolAddress((void**)&h,    g_h);
    cudaGetSymbolAddress((void**)&qkvb, g_qkv);
    cudaGetSymbolAddress((void**)&ob,   g_o);
    cudaGetSymbolAddress((void**)&ff,   g_ff);

    const int flash_smem = 4 * 64 * 65 * 4 + 3 * 64 * 4;  // ~67.3 KB
    cudaFuncSetAttribute(flash_kernel, cudaFuncAttributeMaxDynamicSharedMemorySize, flash_smem);

    // build x
    {
        int total = M_ * D_;
        build_x_kernel<<<(total + 255) / 256, 256>>>(vm, ns, pm, pmW, pmb, vmW, vmb, x);
    }

    const int lnBlocks = (M_ * 32 + 255) / 256;
    const dim3 gQKV(3 * D_ / 64, (M_ + 63) / 64);
    const dim3 gWO (D_ / 64,     (M_ + 63) / 64);
    const dim3 gW1 (DFF_ / 64,   (M_ + 63) / 64);
    const dim3 gW2 (D_ / 64,     (M_ + 63) / 64);
    const dim3 gFL ((S_ + 63) / 64, B_ * H_);

    for (int i = 0; i < NL_; i++) {
        ln_kernel<<<lnBlocks, 256>>>(x, h, ln1s + i * D_, ln1b + i * D_, M_);
        sgemm_kernel<0><<<gQKV, 256>>>(h, Wqkv + (size_t)i * D_ * 3 * D_, bqkv + i * 3 * D_,
                                       qkvb, M_, 3 * D_, D_);
        flash_kernel<<<gFL, 256, flash_smem>>>(qkvb, rel, padm, ob);
        sgemm_kernel<1><<<gWO, 256>>>(ob, Wo + (size_t)i * D_ * D_, bo + i * D_,
                                      x, M_, D_, D_);
        ln_kernel<<<lnBlocks, 256>>>(x, h, ln2s + i * D_, ln2b + i * D_, M_);
        sgemm_kernel<2><<<gW1, 256>>>(h, W1 + (size_t)i * D_ * DFF_, b1 + i * DFF_,
                                      ff, M_, DFF_, D_);
        sgemm_kernel<1><<<gW2, 256>>>(ff, W2 + (size_t)i * DFF_ * D_, b2 + i * D_,
                                      x, M_, D_, DFF_);
    }

    {
        int warps = B_ * NVM_ + B_;
        out_kernel<<<(warps * 32 + 255) / 256, 256>>>(x, outW, outb, crW, crb, (float*)d_out);
    }
}

// round 4
// speedup vs baseline: 1.9077x; 1.9077x over previous
#include <cuda_runtime.h>
#include <cstdint>
#include <cstdio>

// Problem constants
#define B_    4
#define NPM_  200
#define NVM_  1500
#define D_    512
#define H_    8
#define DFF_  2048
#define NL_   3
#define S_    1702           // NPM + NVM + 2
#define M_    (B_ * S_)      // 6808 rows
#define DH_   64
#define RELW_ (NPM_ + NVM_)  // 1700

// ----------------------------------------------------------------------------
// Scratch (static device globals; no allocation allowed)
// ----------------------------------------------------------------------------
__device__ float g_x  [M_ * D_];        // residual stream
__device__ float g_h  [M_ * D_];        // layernorm output (tf32-rounded)
__device__ float g_qkv[M_ * 3 * D_];    // qkv projection (fp32)
__device__ float g_o  [M_ * D_];        // attention output (tf32-rounded)
__device__ float g_ff [M_ * DFF_];      // ffn hidden (tf32-rounded)
// tf32-rounded weights
__device__ float g_wqkv[NL_ * D_ * 3 * D_];
__device__ float g_wo  [NL_ * D_ * D_];
__device__ float g_w1  [NL_ * D_ * DFF_];
__device__ float g_w2  [NL_ * DFF_ * D_];

__device__ __forceinline__ float tf32_rna(float x) {
    uint32_t u;
    asm("cvt.rna.tf32.f32 %0, %1;" : "=r"(u) : "f"(x));
    return __uint_as_float(u);
}

// ----------------------------------------------------------------------------
// Round a weight array to tf32 (rna), vectorized
// ----------------------------------------------------------------------------
__global__ void cvt_tf32_kernel(const float* __restrict__ s, float* __restrict__ d, int n)
{
    int i = (blockIdx.x * blockDim.x + threadIdx.x) * 4;
    if (i >= n) return;
    float4 v = *reinterpret_cast<const float4*>(s + i);
    v.x = tf32_rna(v.x); v.y = tf32_rna(v.y);
    v.z = tf32_rna(v.z); v.w = tf32_rna(v.w);
    *reinterpret_cast<float4*>(d + i) = v;
}

// ----------------------------------------------------------------------------
// build_x
// ----------------------------------------------------------------------------
__global__ void build_x_kernel(const float* __restrict__ vm,
                               const float* __restrict__ ns,
                               const float* __restrict__ pm,
                               const float* __restrict__ pmW, const float* __restrict__ pmb,
                               const float* __restrict__ vmW, const float* __restrict__ vmb,
                               float* __restrict__ x)
{
    int idx = blockIdx.x * blockDim.x + threadIdx.x;
    if (idx >= M_ * D_) return;
    int d = idx & (D_ - 1);
    int sb = idx >> 9;
    int s = sb % S_;
    int b = sb / S_;
    float val;
    if (s == 0) {
        val = ns[b];
    } else if (s <= NPM_) {
        const float* st = pm + ((size_t)b * NPM_ + (s - 1)) * 16;
        val = pmb[d];
        #pragma unroll
        for (int c = 0; c < 16; c++) val += st[c] * pmW[c * D_ + d];
    } else if (s < S_ - 1) {
        const float* st = vm + ((size_t)b * NVM_ + (s - 1 - NPM_)) * 16;
        val = vmb[d];
        #pragma unroll
        for (int c = 0; c < 16; c++) val += st[c] * vmW[c * D_ + d];
    } else {
        val = -1.0f;
    }
    x[idx] = val;
}

// ----------------------------------------------------------------------------
// LayerNorm: one warp per row of 512; output is tf32-rounded (GEMM operand)
// ----------------------------------------------------------------------------
__global__ void ln_kernel(const float* __restrict__ x, float* __restrict__ out,
                          const float* __restrict__ gs, const float* __restrict__ gb,
                          int M)
{
    int warp = (blockIdx.x * blockDim.x + threadIdx.x) >> 5;
    int lane = threadIdx.x & 31;
    if (warp >= M) return;
    const float* row = x + (size_t)warp * D_;
    float4 v[4];
    float sum = 0.f, sq = 0.f;
    #pragma unroll
    for (int j = 0; j < 4; j++) {
        v[j] = *reinterpret_cast<const float4*>(row + (lane + 32 * j) * 4);
        sum += v[j].x + v[j].y + v[j].z + v[j].w;
        sq  += v[j].x * v[j].x + v[j].y * v[j].y + v[j].z * v[j].z + v[j].w * v[j].w;
    }
    #pragma unroll
    for (int o = 16; o; o >>= 1) {
        sum += __shfl_xor_sync(0xffffffffu, sum, o);
        sq  += __shfl_xor_sync(0xffffffffu, sq,  o);
    }
    const float inv = 1.0f / (float)D_;
    float mean = sum * inv;
    float var  = sq * inv - mean * mean;
    float rstd = rsqrtf(var + 1e-5f);
    float* orow = out + (size_t)warp * D_;
    #pragma unroll
    for (int j = 0; j < 4; j++) {
        int c = (lane + 32 * j) * 4;
        float4 r;
        r.x = tf32_rna((v[j].x - mean) * rstd * gs[c + 0] + gb[c + 0]);
        r.y = tf32_rna((v[j].y - mean) * rstd * gs[c + 1] + gb[c + 1]);
        r.z = tf32_rna((v[j].z - mean) * rstd * gs[c + 2] + gb[c + 2]);
        r.w = tf32_rna((v[j].w - mean) * rstd * gs[c + 3] + gb[c + 3]);
        *reinterpret_cast<float4*>(orow + c) = r;
    }
}

// ----------------------------------------------------------------------------
// tf32 tensor-core GEMM: C[M,N] = epi(A[M,K] @ W[K,N] + bias)
//   EPI 0: store fp32   EPI 1: C += (residual)   EPI 2: exact GELU + tf32 round
// Block tile 128x128, BK=16, 128 threads (4 warps, 2x2), warp tile 64x64.
// A,W must be tf32-pre-rounded. N%128==0, K%16==0. M guarded.
// Smem: A [128][20] (pad -> bank (20g+c)%32 is a permutation, conflict-free);
//       B [16][128] with 8-word XOR swizzle col^( (k&3)<<3 ) (conflict-free).
// ----------------------------------------------------------------------------
#define MMA_TF32(d, a, b)                                                        \
    asm volatile(                                                                \
        "mma.sync.aligned.m16n8k8.row.col.f32.tf32.tf32.f32 "                    \
        "{%0,%1,%2,%3}, {%4,%5,%6,%7}, {%8,%9}, {%0,%1,%2,%3};"                  \
        : "+f"((d)[0]), "+f"((d)[1]), "+f"((d)[2]), "+f"((d)[3])                 \
        : "r"((a)[0]), "r"((a)[1]), "r"((a)[2]), "r"((a)[3]),                    \
          "r"((b)[0]), "r"((b)[1]))

template<int EPI>
__global__ void __launch_bounds__(128) mma_gemm_kernel(
    const float* __restrict__ A, const float* __restrict__ W,
    const float* __restrict__ bias, float* __restrict__ C,
    int M, int N, int K)
{
    __shared__ float As[2][128][20];
    __shared__ float Bs[2][16][128];

    const int tid  = threadIdx.x;
    const int lane = tid & 31;
    const int wid  = tid >> 5;
    const int wm   = wid >> 1;
    const int wn   = wid & 1;
    const int g    = lane >> 2;
    const int c    = lane & 3;
    const int row0 = blockIdx.y * 128;
    const int col0 = blockIdx.x * 128;
    const int nk   = K >> 4;

    float acc[4][8][4];
    #pragma unroll
    for (int i = 0; i < 4; i++)
        #pragma unroll
        for (int j = 0; j < 8; j++)
            #pragma unroll
            for (int t = 0; t < 4; t++) acc[i][j][t] = 0.f;

    auto issue = [&](int kt, int buf) {
        const int k0 = kt << 4;
        #pragma unroll
        for (int i = 0; i < 4; i++) {
            int idx = tid + i * 128;
            int r = idx >> 2, q = idx & 3;
            int mr = row0 + r;
            const float* src = A + (size_t)(mr < M ? mr : M - 1) * K + k0 + q * 4;
            uint32_t dst = (uint32_t)__cvta_generic_to_shared(&As[buf][r][q * 4]);
            int sz = (mr < M) ? 16 : 0;
            asm volatile("cp.async.ca.shared.global [%0], [%1], 16, %2;"
                         :: "r"(dst), "l"(src), "r"(sz));
        }
        #pragma unroll
        for (int i = 0; i < 4; i++) {
            int idx = tid + i * 128;
            int k = idx >> 5, nc = idx & 31;
            const float* src = W + (size_t)(k0 + k) * N + col0 + nc * 4;
            int colx = (nc * 4) ^ ((k & 3) << 3);
            uint32_t dst = (uint32_t)__cvta_generic_to_shared(&Bs[buf][k][colx]);
            asm volatile("cp.async.ca.shared.global [%0], [%1], 16;"
                         :: "r"(dst), "l"(src));
        }
        asm volatile("cp.async.commit_group;");
    };

    issue(0, 0);

    for (int kt = 0; kt < nk; kt++) {
        const int buf = kt & 1;
        asm volatile("cp.async.wait_group 0;");
        __syncthreads();
        if (kt + 1 < nk) issue(kt + 1, (kt + 1) & 1);

        #pragma unroll
        for (int ks = 0; ks < 2; ks++) {
            const int kb  = ks * 8 + c;
            const int swz = c << 3;
            uint32_t bf[8][2], af[4][4];
            #pragma unroll
            for (int fn = 0; fn < 8; fn++) {
                int col = wn * 64 + fn * 8 + g;
                bf[fn][0] = __float_as_uint(Bs[buf][kb]    [col ^ swz]);
                bf[fn][1] = __float_as_uint(Bs[buf][kb + 4][col ^ swz]);
            }
            #pragma unroll
            for (int fm = 0; fm < 4; fm++) {
                int r = wm * 64 + fm * 16 + g;
                af[fm][0] = __float_as_uint(As[buf][r]    [kb]);
                af[fm][1] = __float_as_uint(As[buf][r + 8][kb]);
                af[fm][2] = __float_as_uint(As[buf][r]    [kb + 4]);
                af[fm][3] = __float_as_uint(As[buf][r + 8][kb + 4]);
            }
            #pragma unroll
            for (int fm = 0; fm < 4; fm++)
                #pragma unroll
                for (int fn = 0; fn < 8; fn++)
                    MMA_TF32(acc[fm][fn], af[fm], bf[fn]);
        }
        __syncthreads();
    }

    // Epilogue
    const int cc = c * 2;
    #pragma unroll
    for (int fm = 0; fm < 4; fm++) {
        int mA = row0 + wm * 64 + fm * 16 + g;
        int mB = mA + 8;
        #pragma unroll
        for (int fn = 0; fn < 8; fn++) {
            int n = col0 + wn * 64 + fn * 8 + cc;
            float2 b2 = *reinterpret_cast<const float2*>(bias + n);
            float v0 = acc[fm][fn][0] + b2.x;
            float v1 = acc[fm][fn][1] + b2.y;
            float v2 = acc[fm][fn][2] + b2.x;
            float v3 = acc[fm][fn][3] + b2.y;
            if (EPI == 0) {
                if (mA < M) *reinterpret_cast<float2*>(C + (size_t)mA * N + n) = make_float2(v0, v1);
                if (mB < M) *reinterpret_cast<float2*>(C + (size_t)mB * N + n) = make_float2(v2, v3);
            } else if (EPI == 1) {
                if (mA < M) {
                    float2* p = reinterpret_cast<float2*>(C + (size_t)mA * N + n);
                    float2 o = *p; o.x += v0; o.y += v1; *p = o;
                }
                if (mB < M) {
                    float2* p = reinterpret_cast<float2*>(C + (size_t)mB * N + n);
                    float2 o = *p; o.x += v2; o.y += v3; *p = o;
                }
            } else {
                float g0 = tf32_rna(0.5f * v0 * (1.0f + erff(v0 * 0.70710678118654752f)));
                float g1 = tf32_rna(0.5f * v1 * (1.0f + erff(v1 * 0.70710678118654752f)));
                float g2 = tf32_rna(0.5f * v2 * (1.0f + erff(v2 * 0.70710678118654752f)));
                float g3 = tf32_rna(0.5f * v3 * (1.0f + erff(v3 * 0.70710678118654752f)));
                if (mA < M) *reinterpret_cast<float2*>(C + (size_t)mA * N + n) = make_float2(g0, g1);
                if (mB < M) *reinterpret_cast<float2*>(C + (size_t)mB * N + n) = make_float2(g2, g3);
            }
        }
    }
}

// ----------------------------------------------------------------------------
// Flash attention (fp32, unchanged math; output tf32-rounded for Wo GEMM)
// ----------------------------------------------------------------------------
__global__ void flash_kernel(const float* __restrict__ qkv,
                             const int* __restrict__ rel,
                             const unsigned char* __restrict__ padm,
                             float* __restrict__ obuf)
{
    extern __shared__ float smem[];
    float (*Qs)[65] = (float(*)[65])(smem);
    float (*Ks)[65] = (float(*)[65])(smem + 64 * 65);
    float (*Vs)[65] = (float(*)[65])(smem + 2 * 64 * 65);
    float (*Ps)[65] = (float(*)[65])(smem + 3 * 64 * 65);
    int* relq_s = (int*)(smem + 4 * 64 * 65);
    int* relk_s = relq_s + 64;
    int* padk_s = relk_s + 64;

    int tid = threadIdx.x;
    int ty = tid >> 4, tx = tid & 15;
    int bh = blockIdx.y;
    int b = bh / H_, h = bh % H_;
    int qt = blockIdx.x * 64;
    const size_t rs = 3 * D_;
    const float* qbase = qkv + (size_t)b * S_ * rs + h * DH_;
    const float* kbase = qbase + D_;
    const float* vbase = qbase + 2 * D_;

    #pragma unroll
    for (int l = 0; l < 4; l++) {
        int idx = tid + l * 256;
        int r = idx >> 4, c4 = (idx & 15) * 4;
        int q = qt + r;
        float4 v = make_float4(0.f, 0.f, 0.f, 0.f);
        if (q < S_) v = *reinterpret_cast<const float4*>(qbase + (size_t)q * rs + c4);
        Qs[r][c4 + 0] = v.x; Qs[r][c4 + 1] = v.y; Qs[r][c4 + 2] = v.z; Qs[r][c4 + 3] = v.w;
    }
    if (tid < 64) {
        int q = qt + tid;
        relq_s[tid] = (q >= 1 && q < S_ - 1) ? rel[b * RELW_ + q - 1] : -1;
    }
    __syncthreads();

    float m_i[4], l_i[4], o_acc[4][4];
    #pragma unroll
    for (int i = 0; i < 4; i++) {
        m_i[i] = -1e30f; l_i[i] = 0.f;
        #pragma unroll
        for (int j = 0; j < 4; j++) o_acc[i][j] = 0.f;
    }

    for (int kt = 0; kt < S_; kt += 64) {
        #pragma unroll
        for (int l = 0; l < 4; l++) {
            int idx = tid + l * 256;
            int r = idx >> 4, c4 = (idx & 15) * 4;
            int k = kt + r;
            float4 kv = make_float4(0.f, 0.f, 0.f, 0.f);
            float4 vv = make_float4(0.f, 0.f, 0.f, 0.f);
            if (k < S_) {
                kv = *reinterpret_cast<const float4*>(kbase + (size_t)k * rs + c4);
                vv = *reinterpret_cast<const float4*>(vbase + (size_t)k * rs + c4);
            }
            Ks[r][c4 + 0] = kv.x; Ks[r][c4 + 1] = kv.y; Ks[r][c4 + 2] = kv.z; Ks[r][c4 + 3] = kv.w;
            Vs[r][c4 + 0] = vv.x; Vs[r][c4 + 1] = vv.y; Vs[r][c4 + 2] = vv.z; Vs[r][c4 + 3] = vv.w;
        }
        if (tid < 64) {
            int k = kt + tid;
            relk_s[tid] = (k >= 1 && k < S_ - 1) ? rel[b * RELW_ + k - 1] : -2;
            padk_s[tid] = (k >= 1 + NPM_ && k < S_ - 1) ? (int)padm[b * NVM_ + (k - 1 - NPM_)] : 0;
        }
        __syncthreads();

        float sc[4][4];
        #pragma unroll
        for (int i = 0; i < 4; i++)
            #pragma unroll
            for (int j = 0; j < 4; j++) sc[i][j] = 0.f;
        #pragma unroll 8
        for (int d = 0; d < 64; d++) {
            float qv[4], kv[4];
            #pragma unroll
            for (int i = 0; i < 4; i++) qv[i] = Qs[ty + 16 * i][d];
            #pragma unroll
            for (int j = 0; j < 4; j++) kv[j] = Ks[tx + 16 * j][d];
            #pragma unroll
            for (int i = 0; i < 4; i++)
                #pragma unroll
                for (int j = 0; j < 4; j++) sc[i][j] += qv[i] * kv[j];
        }

        #pragma unroll
        for (int i = 0; i < 4; i++) {
            int q = qt + ty + 16 * i;
            int rq = relq_s[ty + 16 * i];
            bool innerq = (q >= 1 && q < S_ - 1);
            float rowmax = -1e30f;
            #pragma unroll
            for (int j = 0; j < 4; j++) {
                int c = tx + 16 * j;
                int k = kt + c;
                float val = sc[i][j] * 0.125f;
                bool masked = (innerq && k >= 1 && k < S_ - 1 && rq != relk_s[c]);
                masked = masked || (padk_s[c] != 0);
                if (k >= S_)      val = -1e30f;
                else if (masked)  val = -1e9f;
                sc[i][j] = val;
                rowmax = fmaxf(rowmax, val);
            }
            #pragma unroll
            for (int o = 8; o; o >>= 1)
                rowmax = fmaxf(rowmax, __shfl_xor_sync(0xffffffffu, rowmax, o, 16));
            float mnew = fmaxf(m_i[i], rowmax);
            float corr = __expf(m_i[i] - mnew);
            float rsum = 0.f;
            #pragma unroll
            for (int j = 0; j < 4; j++) {
                float p = __expf(sc[i][j] - mnew);
                sc[i][j] = p;
                rsum += p;
            }
            #pragma unroll
            for (int o = 8; o; o >>= 1)
                rsum += __shfl_xor_sync(0xffffffffu, rsum, o, 16);
            l_i[i] = l_i[i] * corr + rsum;
            #pragma unroll
            for (int j = 0; j < 4; j++) o_acc[i][j] *= corr;
            m_i[i] = mnew;
        }

        #pragma unroll
        for (int i = 0; i < 4; i++)
            #pragma unroll
            for (int j = 0; j < 4; j++) Ps[ty + 16 * i][tx + 16 * j] = sc[i][j];
        __syncthreads();

        #pragma unroll 8
        for (int cI = 0; cI < 64; cI++) {
            float pv[4], vv[4];
            #pragma unroll
            for (int i = 0; i < 4; i++) pv[i] = Ps[ty + 16 * i][cI];
            #pragma unroll
            for (int j = 0; j < 4; j++) vv[j] = Vs[cI][tx + 16 * j];
            #pragma unroll
            for (int i = 0; i < 4; i++)
                #pragma unroll
                for (int j = 0; j < 4; j++) o_acc[i][j] += pv[i] * vv[j];
        }
        __syncthreads();
    }

    #pragma unroll
    for (int i = 0; i < 4; i++) {
        int q = qt + ty + 16 * i;
        if (q >= S_) continue;
        float inv = 1.0f / l_i[i];
        float* dst = obuf + ((size_t)b * S_ + q) * D_ + h * DH_;
        #pragma unroll
        for (int j = 0; j < 4; j++) dst[tx + 16 * j] = tf32_rna(o_acc[i][j] * inv);
    }
}

// ----------------------------------------------------------------------------
// Output heads
// ----------------------------------------------------------------------------
__global__ void out_kernel(const float* __restrict__ x,
                           const float* __restrict__ outW, const float* __restrict__ outb,
                           const float* __restrict__ crW,  const float* __restrict__ crb,
                           float* __restrict__ out)
{
    int warp = (blockIdx.x * blockDim.x + threadIdx.x) >> 5;
    int lane = threadIdx.x & 31;
    const int nscore = B_ * NVM_;
    if (warp >= nscore + B_) return;
    int b, s;
    const float* w;
    float bias;
    float* dst;
    if (warp < nscore) {
        b = warp / NVM_;
        s = 1 + NPM_ + (warp % NVM_);
        w = outW; bias = outb[0];
        dst = out + warp;
    } else {
        b = warp - nscore;
        s = S_ - 1;
        w = crW; bias = crb[0];
        dst = out + nscore + b;
    }
    const float* row = x + ((size_t)b * S_ + s) * D_;
    float sum = 0.f;
    for (int c = lane; c < D_; c += 32) sum += row[c] * w[c];
    #pragma unroll
    for (int o = 16; o; o >>= 1) sum += __shfl_xor_sync(0xffffffffu, sum, o);
    if (lane == 0) *dst = sum + bias;
}

// ----------------------------------------------------------------------------
// Host launcher
// ----------------------------------------------------------------------------
extern "C" void kernel_launch(void* const* d_in, const int* in_sizes, int n_in,
                              void* d_out, int out_size)
{
    const float* vm   = (const float*)d_in[0];
    const float* ns   = (const float*)d_in[1];
    const float* pm   = (const float*)d_in[2];
    const int*   rel  = (const int*)  d_in[3];
    const unsigned char* padm = (const unsigned char*)d_in[4];
    const float* pmW  = (const float*)d_in[5];
    const float* pmb  = (const float*)d_in[6];
    const float* vmW  = (const float*)d_in[7];
    const float* vmb  = (const float*)d_in[8];
    const float* ln1s = (const float*)d_in[9];
    const float* ln1b = (const float*)d_in[10];
    const float* Wqkv = (const float*)d_in[11];
    const float* bqkv = (const float*)d_in[12];
    const float* Wo   = (const float*)d_in[13];
    const float* bo   = (const float*)d_in[14];
    const float* ln2s = (const float*)d_in[15];
    const float* ln2b = (const float*)d_in[16];
    const float* W1   = (const float*)d_in[17];
    const float* b1   = (const float*)d_in[18];
    const float* W2   = (const float*)d_in[19];
    const float* b2   = (const float*)d_in[20];
    const float* outW = (const float*)d_in[21];
    const float* outb = (const float*)d_in[22];
    const float* crW  = (const float*)d_in[23];
    const float* crb  = (const float*)d_in[24];

    float *x, *h, *qkvb, *ob, *ff, *wqkv, *wo, *w1, *w2;
    cudaGetSymbolAddress((void**)&x,    g_x);
    cudaGetSymbolAddress((void**)&h,    g_h);
    cudaGetSymbolAddress((void**)&qkvb, g_qkv);
    cudaGetSymbolAddress((void**)&ob,   g_o);
    cudaGetSymbolAddress((void**)&ff,   g_ff);
    cudaGetSymbolAddress((void**)&wqkv, g_wqkv);
    cudaGetSymbolAddress((void**)&wo,   g_wo);
    cudaGetSymbolAddress((void**)&w1,   g_w1);
    cudaGetSymbolAddress((void**)&w2,   g_w2);

    const int flash_smem = 4 * 64 * 65 * 4 + 3 * 64 * 4;  // ~67.3 KB
    cudaFuncSetAttribute(flash_kernel, cudaFuncAttributeMaxDynamicSharedMemorySize, flash_smem);

    // tf32-round weights once per launch
    {
        int n;
        n = NL_ * D_ * 3 * D_; cvt_tf32_kernel<<<(n / 4 + 255) / 256, 256>>>(Wqkv, wqkv, n);
        n = NL_ * D_ * D_;     cvt_tf32_kernel<<<(n / 4 + 255) / 256, 256>>>(Wo,   wo,   n);
        n = NL_ * D_ * DFF_;   cvt_tf32_kernel<<<(n / 4 + 255) / 256, 256>>>(W1,   w1,   n);
        n = NL_ * DFF_ * D_;   cvt_tf32_kernel<<<(n / 4 + 255) / 256, 256>>>(W2,   w2,   n);
    }

    // build x
    {
        int total = M_ * D_;
        build_x_kernel<<<(total + 255) / 256, 256>>>(vm, ns, pm, pmW, pmb, vmW, vmb, x);
    }

    const int lnBlocks = (M_ * 32 + 255) / 256;
    const int MB = (M_ + 127) / 128;   // 54
    const dim3 gQKV(3 * D_ / 128, MB);
    const dim3 gWO (D_ / 128,     MB);
    const dim3 gW1 (DFF_ / 128,   MB);
    const dim3 gW2 (D_ / 128,     MB);
    const dim3 gFL ((S_ + 63) / 64, B_ * H_);

    for (int i = 0; i < NL_; i++) {
        ln_kernel<<<lnBlocks, 256>>>(x, h, ln1s + i * D_, ln1b + i * D_, M_);
        mma_gemm_kernel<0><<<gQKV, 128>>>(h, wqkv + (size_t)i * D_ * 3 * D_, bqkv + i * 3 * D_,
                                          qkvb, M_, 3 * D_, D_);
        flash_kernel<<<gFL, 256, flash_smem>>>(qkvb, rel, padm, ob);
        mma_gemm_kernel<1><<<gWO, 128>>>(ob, wo + (size_t)i * D_ * D_, bo + i * D_,
                                         x, M_, D_, D_);
        ln_kernel<<<lnBlocks, 256>>>(x, h, ln2s + i * D_, ln2b + i * D_, M_);
        mma_gemm_kernel<2><<<gW1, 128>>>(h, w1 + (size_t)i * D_ * DFF_, b1 + i * DFF_,
                                         ff, M_, DFF_, D_);
        mma_gemm_kernel<1><<<gW2, 128>>>(ff, w2 + (size_t)i * DFF_ * D_, b2 + i * D_,
                                         x, M_, D_, DFF_);
    }

    {
        int warps = B_ * NVM_ + B_;
        out_kernel<<<(warps * 32 + 255) / 256, 256>>>(x, outW, outb, crW, crb, (float*)d_out);
    }
}

// round 5
// speedup vs baseline: 4.1466x; 2.1737x over previous
#include <cuda_runtime.h>
#include <cstdint>
#include <cstdio>

// Problem constants
#define B_    4
#define NPM_  200
#define NVM_  1500
#define D_    512
#define H_    8
#define DFF_  2048
#define NL_   3
#define S_    1702           // NPM + NVM + 2
#define M_    (B_ * S_)      // 6808 rows
#define DH_   64
#define RELW_ (NPM_ + NVM_)  // 1700

// ----------------------------------------------------------------------------
// Scratch (static device globals; no allocation allowed)
// ----------------------------------------------------------------------------
__device__ float g_x  [M_ * D_];
__device__ float g_h  [M_ * D_];
__device__ float g_qkv[M_ * 3 * D_];
__device__ float g_o  [M_ * D_];
__device__ float g_ff [M_ * DFF_];
__device__ float g_wqkv[NL_ * D_ * 3 * D_];
__device__ float g_wo  [NL_ * D_ * D_];
__device__ float g_w1  [NL_ * D_ * DFF_];
__device__ float g_w2  [NL_ * DFF_ * D_];
// attention sparsity structure (computed once per launch; rel is layer-invariant)
__device__ int g_sidx[B_ * RELW_];          // token positions sorted by rel group
__device__ int g_goff[B_ * (NPM_ + 1)];     // group offsets (201 per batch)

__device__ __forceinline__ float tf32_rna(float x) {
    uint32_t u;
    asm("cvt.rna.tf32.f32 %0, %1;" : "=r"(u) : "f"(x));
    return __uint_as_float(u);
}

// ----------------------------------------------------------------------------
// Round a weight array to tf32 (rna), vectorized
// ----------------------------------------------------------------------------
__global__ void cvt_tf32_kernel(const float* __restrict__ s, float* __restrict__ d, int n)
{
    int i = (blockIdx.x * blockDim.x + threadIdx.x) * 4;
    if (i >= n) return;
    float4 v = *reinterpret_cast<const float4*>(s + i);
    v.x = tf32_rna(v.x); v.y = tf32_rna(v.y);
    v.z = tf32_rna(v.z); v.w = tf32_rna(v.w);
    *reinterpret_cast<float4*>(d + i) = v;
}

// ----------------------------------------------------------------------------
// build_x
// ----------------------------------------------------------------------------
__global__ void build_x_kernel(const float* __restrict__ vm,
                               const float* __restrict__ ns,
                               const float* __restrict__ pm,
                               const float* __restrict__ pmW, const float* __restrict__ pmb,
                               const float* __restrict__ vmW, const float* __restrict__ vmb,
                               float* __restrict__ x)
{
    int idx = blockIdx.x * blockDim.x + threadIdx.x;
    if (idx >= M_ * D_) return;
    int d = idx & (D_ - 1);
    int sb = idx >> 9;
    int s = sb % S_;
    int b = sb / S_;
    float val;
    if (s == 0) {
        val = ns[b];
    } else if (s <= NPM_) {
        const float* st = pm + ((size_t)b * NPM_ + (s - 1)) * 16;
        val = pmb[d];
        #pragma unroll
        for (int c = 0; c < 16; c++) val += st[c] * pmW[c * D_ + d];
    } else if (s < S_ - 1) {
        const float* st = vm + ((size_t)b * NVM_ + (s - 1 - NPM_)) * 16;
        val = vmb[d];
        #pragma unroll
        for (int c = 0; c < 16; c++) val += st[c] * vmW[c * D_ + d];
    } else {
        val = -1.0f;
    }
    x[idx] = val;
}

// ----------------------------------------------------------------------------
// Counting sort of inner tokens by rel value (one block per batch).
// Deterministic: parallel histogram (counts only), sequential stable scatter.
// ----------------------------------------------------------------------------
__global__ void sort_kernel(const int* __restrict__ rel, int* __restrict__ sidx,
                            int* __restrict__ goff)
{
    __shared__ int hist[NPM_];
    __shared__ int offs[NPM_ + 1];
    __shared__ int relv[RELW_];
    int b = blockIdx.x, tid = threadIdx.x;
    for (int i = tid; i < NPM_; i += blockDim.x) hist[i] = 0;
    __syncthreads();
    for (int i = tid; i < RELW_; i += blockDim.x) {
        int r = rel[b * RELW_ + i];
        relv[i] = r;
        atomicAdd(&hist[r], 1);
    }
    __syncthreads();
    if (tid == 0) {
        int acc = 0;
        for (int r = 0; r < NPM_; r++) {
            offs[r] = acc;
            goff[b * (NPM_ + 1) + r] = acc;
            acc += hist[r];
        }
        goff[b * (NPM_ + 1) + NPM_] = acc;
        int* out = sidx + b * RELW_;
        for (int p = 0; p < RELW_; p++) {
            int r = relv[p];
            out[offs[r]++] = p + 1;   // token position
        }
    }
}

// ----------------------------------------------------------------------------
// LayerNorm: one warp per row of 512; output tf32-rounded (GEMM operand)
// ----------------------------------------------------------------------------
__global__ void ln_kernel(const float* __restrict__ x, float* __restrict__ out,
                          const float* __restrict__ gs, const float* __restrict__ gb,
                          int M)
{
    int warp = (blockIdx.x * blockDim.x + threadIdx.x) >> 5;
    int lane = threadIdx.x & 31;
    if (warp >= M) return;
    const float* row = x + (size_t)warp * D_;
    float4 v[4];
    float sum = 0.f, sq = 0.f;
    #pragma unroll
    for (int j = 0; j < 4; j++) {
        v[j] = *reinterpret_cast<const float4*>(row + (lane + 32 * j) * 4);
        sum += v[j].x + v[j].y + v[j].z + v[j].w;
        sq  += v[j].x * v[j].x + v[j].y * v[j].y + v[j].z * v[j].z + v[j].w * v[j].w;
    }
    #pragma unroll
    for (int o = 16; o; o >>= 1) {
        sum += __shfl_xor_sync(0xffffffffu, sum, o);
        sq  += __shfl_xor_sync(0xffffffffu, sq,  o);
    }
    const float inv = 1.0f / (float)D_;
    float mean = sum * inv;
    float var  = sq * inv - mean * mean;
    float rstd = rsqrtf(var + 1e-5f);
    float* orow = out + (size_t)warp * D_;
    #pragma unroll
    for (int j = 0; j < 4; j++) {
        int c = (lane + 32 * j) * 4;
        float4 r;
        r.x = tf32_rna((v[j].x - mean) * rstd * gs[c + 0] + gb[c + 0]);
        r.y = tf32_rna((v[j].y - mean) * rstd * gs[c + 1] + gb[c + 1]);
        r.z = tf32_rna((v[j].z - mean) * rstd * gs[c + 2] + gb[c + 2]);
        r.w = tf32_rna((v[j].w - mean) * rstd * gs[c + 3] + gb[c + 3]);
        *reinterpret_cast<float4*>(orow + c) = r;
    }
}

// ----------------------------------------------------------------------------
// tf32 tensor-core GEMM (unchanged from R3)
// ----------------------------------------------------------------------------
#define MMA_TF32(d, a, b)                                                        \
    asm volatile(                                                                \
        "mma.sync.aligned.m16n8k8.row.col.f32.tf32.tf32.f32 "                    \
        "{%0,%1,%2,%3}, {%4,%5,%6,%7}, {%8,%9}, {%0,%1,%2,%3};"                  \
        : "+f"((d)[0]), "+f"((d)[1]), "+f"((d)[2]), "+f"((d)[3])                 \
        : "r"((a)[0]), "r"((a)[1]), "r"((a)[2]), "r"((a)[3]),                    \
          "r"((b)[0]), "r"((b)[1]))

template<int EPI>
__global__ void __launch_bounds__(128) mma_gemm_kernel(
    const float* __restrict__ A, const float* __restrict__ W,
    const float* __restrict__ bias, float* __restrict__ C,
    int M, int N, int K)
{
    __shared__ float As[2][128][20];
    __shared__ float Bs[2][16][128];

    const int tid  = threadIdx.x;
    const int lane = tid & 31;
    const int wid  = tid >> 5;
    const int wm   = wid >> 1;
    const int wn   = wid & 1;
    const int g    = lane >> 2;
    const int c    = lane & 3;
    const int row0 = blockIdx.y * 128;
    const int col0 = blockIdx.x * 128;
    const int nk   = K >> 4;

    float acc[4][8][4];
    #pragma unroll
    for (int i = 0; i < 4; i++)
        #pragma unroll
        for (int j = 0; j < 8; j++)
            #pragma unroll
            for (int t = 0; t < 4; t++) acc[i][j][t] = 0.f;

    auto issue = [&](int kt, int buf) {
        const int k0 = kt << 4;
        #pragma unroll
        for (int i = 0; i < 4; i++) {
            int idx = tid + i * 128;
            int r = idx >> 2, q = idx & 3;
            int mr = row0 + r;
            const float* src = A + (size_t)(mr < M ? mr : M - 1) * K + k0 + q * 4;
            uint32_t dst = (uint32_t)__cvta_generic_to_shared(&As[buf][r][q * 4]);
            int sz = (mr < M) ? 16 : 0;
            asm volatile("cp.async.ca.shared.global [%0], [%1], 16, %2;"
                         :: "r"(dst), "l"(src), "r"(sz));
        }
        #pragma unroll
        for (int i = 0; i < 4; i++) {
            int idx = tid + i * 128;
            int k = idx >> 5, nc = idx & 31;
            const float* src = W + (size_t)(k0 + k) * N + col0 + nc * 4;
            int colx = (nc * 4) ^ ((k & 3) << 3);
            uint32_t dst = (uint32_t)__cvta_generic_to_shared(&Bs[buf][k][colx]);
            asm volatile("cp.async.ca.shared.global [%0], [%1], 16;"
                         :: "r"(dst), "l"(src));
        }
        asm volatile("cp.async.commit_group;");
    };

    issue(0, 0);

    for (int kt = 0; kt < nk; kt++) {
        const int buf = kt & 1;
        asm volatile("cp.async.wait_group 0;");
        __syncthreads();
        if (kt + 1 < nk) issue(kt + 1, (kt + 1) & 1);

        #pragma unroll
        for (int ks = 0; ks < 2; ks++) {
            const int kb  = ks * 8 + c;
            const int swz = c << 3;
            uint32_t bf[8][2], af[4][4];
            #pragma unroll
            for (int fn = 0; fn < 8; fn++) {
                int col = wn * 64 + fn * 8 + g;
                bf[fn][0] = __float_as_uint(Bs[buf][kb]    [col ^ swz]);
                bf[fn][1] = __float_as_uint(Bs[buf][kb + 4][col ^ swz]);
            }
            #pragma unroll
            for (int fm = 0; fm < 4; fm++) {
                int r = wm * 64 + fm * 16 + g;
                af[fm][0] = __float_as_uint(As[buf][r]    [kb]);
                af[fm][1] = __float_as_uint(As[buf][r + 8][kb]);
                af[fm][2] = __float_as_uint(As[buf][r]    [kb + 4]);
                af[fm][3] = __float_as_uint(As[buf][r + 8][kb + 4]);
            }
            #pragma unroll
            for (int fm = 0; fm < 4; fm++)
                #pragma unroll
                for (int fn = 0; fn < 8; fn++)
                    MMA_TF32(acc[fm][fn], af[fm], bf[fn]);
        }
        __syncthreads();
    }

    const int cc = c * 2;
    #pragma unroll
    for (int fm = 0; fm < 4; fm++) {
        int mA = row0 + wm * 64 + fm * 16 + g;
        int mB = mA + 8;
        #pragma unroll
        for (int fn = 0; fn < 8; fn++) {
            int n = col0 + wn * 64 + fn * 8 + cc;
            float2 b2 = *reinterpret_cast<const float2*>(bias + n);
            float v0 = acc[fm][fn][0] + b2.x;
            float v1 = acc[fm][fn][1] + b2.y;
            float v2 = acc[fm][fn][2] + b2.x;
            float v3 = acc[fm][fn][3] + b2.y;
            if (EPI == 0) {
                if (mA < M) *reinterpret_cast<float2*>(C + (size_t)mA * N + n) = make_float2(v0, v1);
                if (mB < M) *reinterpret_cast<float2*>(C + (size_t)mB * N + n) = make_float2(v2, v3);
            } else if (EPI == 1) {
                if (mA < M) {
                    float2* p = reinterpret_cast<float2*>(C + (size_t)mA * N + n);
                    float2 o = *p; o.x += v0; o.y += v1; *p = o;
                }
                if (mB < M) {
                    float2* p = reinterpret_cast<float2*>(C + (size_t)mB * N + n);
                    float2 o = *p; o.x += v2; o.y += v3; *p = o;
                }
            } else {
                float g0 = tf32_rna(0.5f * v0 * (1.0f + erff(v0 * 0.70710678118654752f)));
                float g1 = tf32_rna(0.5f * v1 * (1.0f + erff(v1 * 0.70710678118654752f)));
                float g2 = tf32_rna(0.5f * v2 * (1.0f + erff(v2 * 0.70710678118654752f)));
                float g3 = tf32_rna(0.5f * v3 * (1.0f + erff(v3 * 0.70710678118654752f)));
                if (mA < M) *reinterpret_cast<float2*>(C + (size_t)mA * N + n) = make_float2(g0, g1);
                if (mB < M) *reinterpret_cast<float2*>(C + (size_t)mB * N + n) = make_float2(g2, g3);
            }
        }
    }
}

// ----------------------------------------------------------------------------
// Sparse group attention: one warp per (b, h, inner query).
// Keys = {0} ∪ {S-1} ∪ {k : rel[k]==rel[q], not padded}. Online softmax, fp32.
// Masked entries in the reference contribute exp(-1e9 - m) == 0 exactly, so
// skipping them is bit-compatible within fp32 tolerance.
// ----------------------------------------------------------------------------
__global__ void grp_attn_kernel(const float* __restrict__ qkv,
                                const int* __restrict__ rel,
                                const int* __restrict__ sidx,
                                const int* __restrict__ goff,
                                const unsigned char* __restrict__ padm,
                                float* __restrict__ obuf)
{
    int gw = (blockIdx.x * blockDim.x + threadIdx.x) >> 5;
    int lane = threadIdx.x & 31;
    if (gw >= B_ * H_ * RELW_) return;
    int qi = gw % RELW_;
    int bh = gw / RELW_;
    int h = bh % H_, b = bh / H_;
    int qpos = 1 + qi;

    const size_t rs = 3 * D_;
    const float* base = qkv + (size_t)b * S_ * rs + h * DH_;
    const float* qrow = base + (size_t)qpos * rs;
    float q0 = qrow[lane], q1 = qrow[lane + 32];

    int r   = rel[b * RELW_ + qi];
    int beg = goff[b * (NPM_ + 1) + r];
    int end = goff[b * (NPM_ + 1) + r + 1];

    float m = -1e30f, l = 0.f, o0 = 0.f, o1 = 0.f;

    for (int it = -2; it < end - beg; it++) {
        int kpos;
        if (it == -2)      kpos = 0;
        else if (it == -1) kpos = S_ - 1;
        else {
            kpos = sidx[b * RELW_ + beg + it];
            if (kpos > NPM_ && padm[b * NVM_ + kpos - 1 - NPM_]) continue;
        }
        const float* krow = base + (size_t)kpos * rs + D_;
        float p = q0 * krow[lane] + q1 * krow[lane + 32];
        #pragma unroll
        for (int o = 16; o; o >>= 1) p += __shfl_xor_sync(0xffffffffu, p, o);
        float s = p * 0.125f;
        float mn = fmaxf(m, s);
        float corr = __expf(m - mn);
        float pe   = __expf(s - mn);
        const float* vrow = krow + D_;
        o0 = o0 * corr + pe * vrow[lane];
        o1 = o1 * corr + pe * vrow[lane + 32];
        l  = l * corr + pe;
        m  = mn;
    }

    float inv = 1.0f / l;
    float* dst = obuf + ((size_t)b * S_ + qpos) * D_ + h * DH_;
    dst[lane]      = tf32_rna(o0 * inv);
    dst[lane + 32] = tf32_rna(o1 * inv);
}

// ----------------------------------------------------------------------------
// Dense rows: queries q in {0, S-1} attend to all non-padded keys.
// One block per (b, h, qsel); 8 warps stripe the keys, partial-softmax merge.
// ----------------------------------------------------------------------------
__global__ void dense_attn_kernel(const float* __restrict__ qkv,
                                  const unsigned char* __restrict__ padm,
                                  float* __restrict__ obuf)
{
    __shared__ float sm[8], sl[8], so[8][64];
    int bx = blockIdx.x;
    int qsel = bx & 1;
    int h = (bx >> 1) & (H_ - 1);
    int b = bx >> 4;
    int qpos = qsel ? (S_ - 1) : 0;
    int warp = threadIdx.x >> 5, lane = threadIdx.x & 31;

    const size_t rs = 3 * D_;
    const float* base = qkv + (size_t)b * S_ * rs + h * DH_;
    const float* qrow = base + (size_t)qpos * rs;
    float q0 = qrow[lane], q1 = qrow[lane + 32];

    float m = -1e30f, l = 0.f, o0 = 0.f, o1 = 0.f;
    for (int k = warp; k < S_; k += 8) {
        if (k > NPM_ && k < S_ - 1 && padm[b * NVM_ + k - 1 - NPM_]) continue;
        const float* krow = base + (size_t)k * rs + D_;
        float p = q0 * krow[lane] + q1 * krow[lane + 32];
        #pragma unroll
        for (int o = 16; o; o >>= 1) p += __shfl_xor_sync(0xffffffffu, p, o);
        float s = p * 0.125f;
        float mn = fmaxf(m, s);
        float corr = __expf(m - mn);
        float pe   = __expf(s - mn);
        const float* vrow = krow + D_;
        o0 = o0 * corr + pe * vrow[lane];
        o1 = o1 * corr + pe * vrow[lane + 32];
        l  = l * corr + pe;
        m  = mn;
    }
    if (lane == 0) { sm[warp] = m; sl[warp] = l; }
    so[warp][lane]      = o0;
    so[warp][lane + 32] = o1;
    __syncthreads();

    if (threadIdx.x < 64) {
        float M = -1e30f;
        #pragma unroll
        for (int w = 0; w < 8; w++) M = fmaxf(M, sm[w]);
        float L = 0.f, ov = 0.f;
        #pragma unroll
        for (int w = 0; w < 8; w++) {
            float e = __expf(sm[w] - M);
            L  += sl[w] * e;
            ov += so[w][threadIdx.x] * e;
        }
        float* dst = obuf + ((size_t)b * S_ + qpos) * D_ + h * DH_;
        dst[threadIdx.x] = tf32_rna(ov / L);
    }
}

// ----------------------------------------------------------------------------
// Output heads
// ----------------------------------------------------------------------------
__global__ void out_kernel(const float* __restrict__ x,
                           const float* __restrict__ outW, const float* __restrict__ outb,
                           const float* __restrict__ crW,  const float* __restrict__ crb,
                           float* __restrict__ out)
{
    int warp = (blockIdx.x * blockDim.x + threadIdx.x) >> 5;
    int lane = threadIdx.x & 31;
    const int nscore = B_ * NVM_;
    if (warp >= nscore + B_) return;
    int b, s;
    const float* w;
    float bias;
    float* dst;
    if (warp < nscore) {
        b = warp / NVM_;
        s = 1 + NPM_ + (warp % NVM_);
        w = outW; bias = outb[0];
        dst = out + warp;
    } else {
        b = warp - nscore;
        s = S_ - 1;
        w = crW; bias = crb[0];
        dst = out + nscore + b;
    }
    const float* row = x + ((size_t)b * S_ + s) * D_;
    float sum = 0.f;
    for (int c = lane; c < D_; c += 32) sum += row[c] * w[c];
    #pragma unroll
    for (int o = 16; o; o >>= 1) sum += __shfl_xor_sync(0xffffffffu, sum, o);
    if (lane == 0) *dst = sum + bias;
}

// ----------------------------------------------------------------------------
// Host launcher
// ----------------------------------------------------------------------------
extern "C" void kernel_launch(void* const* d_in, const int* in_sizes, int n_in,
                              void* d_out, int out_size)
{
    const float* vm   = (const float*)d_in[0];
    const float* ns   = (const float*)d_in[1];
    const float* pm   = (const float*)d_in[2];
    const int*   rel  = (const int*)  d_in[3];
    const unsigned char* padm = (const unsigned char*)d_in[4];
    const float* pmW  = (const float*)d_in[5];
    const float* pmb  = (const float*)d_in[6];
    const float* vmW  = (const float*)d_in[7];
    const float* vmb  = (const float*)d_in[8];
    const float* ln1s = (const float*)d_in[9];
    const float* ln1b = (const float*)d_in[10];
    const float* Wqkv = (const float*)d_in[11];
    const float* bqkv = (const float*)d_in[12];
    const float* Wo   = (const float*)d_in[13];
    const float* bo   = (const float*)d_in[14];
    const float* ln2s = (const float*)d_in[15];
    const float* ln2b = (const float*)d_in[16];
    const float* W1   = (const float*)d_in[17];
    const float* b1   = (const float*)d_in[18];
    const float* W2   = (const float*)d_in[19];
    const float* b2   = (const float*)d_in[20];
    const float* outW = (const float*)d_in[21];
    const float* outb = (const float*)d_in[22];
    const float* crW  = (const float*)d_in[23];
    const float* crb  = (const float*)d_in[24];

    float *x, *h, *qkvb, *ob, *ff, *wqkv, *wo, *w1, *w2;
    int *sidx, *goff;
    cudaGetSymbolAddress((void**)&x,    g_x);
    cudaGetSymbolAddress((void**)&h,    g_h);
    cudaGetSymbolAddress((void**)&qkvb, g_qkv);
    cudaGetSymbolAddress((void**)&ob,   g_o);
    cudaGetSymbolAddress((void**)&ff,   g_ff);
    cudaGetSymbolAddress((void**)&wqkv, g_wqkv);
    cudaGetSymbolAddress((void**)&wo,   g_wo);
    cudaGetSymbolAddress((void**)&w1,   g_w1);
    cudaGetSymbolAddress((void**)&w2,   g_w2);
    cudaGetSymbolAddress((void**)&sidx, g_sidx);
    cudaGetSymbolAddress((void**)&goff, g_goff);

    // tf32-round weights once per launch
    {
        int n;
        n = NL_ * D_ * 3 * D_; cvt_tf32_kernel<<<(n / 4 + 255) / 256, 256>>>(Wqkv, wqkv, n);
        n = NL_ * D_ * D_;     cvt_tf32_kernel<<<(n / 4 + 255) / 256, 256>>>(Wo,   wo,   n);
        n = NL_ * D_ * DFF_;   cvt_tf32_kernel<<<(n / 4 + 255) / 256, 256>>>(W1,   w1,   n);
        n = NL_ * DFF_ * D_;   cvt_tf32_kernel<<<(n / 4 + 255) / 256, 256>>>(W2,   w2,   n);
    }

    // group structure (rel is layer-invariant)
    sort_kernel<<<B_, 256>>>(rel, sidx, goff);

    // build x
    {
        int total = M_ * D_;
        build_x_kernel<<<(total + 255) / 256, 256>>>(vm, ns, pm, pmW, pmb, vmW, vmb, x);
    }

    const int lnBlocks = (M_ * 32 + 255) / 256;
    const int MB = (M_ + 127) / 128;   // 54
    const dim3 gQKV(3 * D_ / 128, MB);
    const dim3 gWO (D_ / 128,     MB);
    const dim3 gW1 (DFF_ / 128,   MB);
    const dim3 gW2 (D_ / 128,     MB);
    const int grpBlocks = (B_ * H_ * RELW_) / 8;   // 6800 (exact: 54400 warps)
    const int denseBlocks = B_ * H_ * 2;           // 64

    for (int i = 0; i < NL_; i++) {
        ln_kernel<<<lnBlocks, 256>>>(x, h, ln1s + i * D_, ln1b + i * D_, M_);
        mma_gemm_kernel<0><<<gQKV, 128>>>(h, wqkv + (size_t)i * D_ * 3 * D_, bqkv + i * 3 * D_,
                                          qkvb, M_, 3 * D_, D_);
        grp_attn_kernel<<<grpBlocks, 256>>>(qkvb, rel, sidx, goff, padm, ob);
        dense_attn_kernel<<<denseBlocks, 256>>>(qkvb, padm, ob);
        mma_gemm_kernel<1><<<gWO, 128>>>(ob, wo + (size_t)i * D_ * D_, bo + i * D_,
                                         x, M_, D_, D_);
        ln_kernel<<<lnBlocks, 256>>>(x, h, ln2s + i * D_, ln2b + i * D_, M_);
        mma_gemm_kernel<2><<<gW1, 128>>>(h, w1 + (size_t)i * D_ * DFF_, b1 + i * DFF_,
                                         ff, M_, DFF_, D_);
        mma_gemm_kernel<1><<<gW2, 128>>>(ff, w2 + (size_t)i * DFF_ * D_, b2 + i * D_,
                                         x, M_, D_, DFF_);
    }

    {
        int warps = B_ * NVM_ + B_;
        out_kernel<<<(warps * 32 + 255) / 256, 256>>>(x, outW, outb, crW, crb, (float*)d_out);
    }
}

// round 7
// speedup vs baseline: 5.5239x; 1.3321x over previous
#include <cuda_runtime.h>
#include <cuda_fp16.h>
#include <cstdint>

// Problem constants
#define B_    4
#define NPM_  200
#define NVM_  1500
#define D_    512
#define H_    8
#define DFF_  2048
#define NL_   3
#define S_    1702           // NPM + NVM + 2
#define M_    (B_ * S_)      // 6808 rows
#define DH_   64
#define RELW_ (NPM_ + NVM_)  // 1700

// ----------------------------------------------------------------------------
// Scratch (static device globals; no allocation allowed)
// ----------------------------------------------------------------------------
__device__ float  g_x  [M_ * D_];       // residual stream (fp32)
__device__ __half g_h  [M_ * D_];       // layernorm output (GEMM A operand)
__device__ float  g_qkv[M_ * 3 * D_];   // qkv projection (fp32, attention reads)
__device__ __half g_o  [M_ * D_];       // attention output (GEMM A operand)
__device__ __half g_ff [M_ * DFF_];     // ffn hidden (GEMM A operand)
// transposed + fp16 weights, [N][K] per layer
__device__ __half g_wqkv[NL_ * D_ * 3 * D_];
__device__ __half g_wo  [NL_ * D_ * D_];
__device__ __half g_w1  [NL_ * D_ * DFF_];
__device__ __half g_w2  [NL_ * DFF_ * D_];
// attention sparsity structure
__device__ int g_sidx[B_ * RELW_];
__device__ int g_goff[B_ * (NPM_ + 1)];

// ----------------------------------------------------------------------------
// Weight transpose + fp16 convert: W[K][N] fp32 -> Wt[N][K] fp16
// ----------------------------------------------------------------------------
__global__ void transpose_h_kernel(const float* __restrict__ W, __half* __restrict__ Wt,
                                   int K, int N)
{
    __shared__ float t[32][33];
    int n0 = blockIdx.x * 32, k0 = blockIdx.y * 32;
    int tx = threadIdx.x, ty = threadIdx.y;
    #pragma unroll
    for (int r = ty; r < 32; r += 8)
        t[r][tx] = W[(size_t)(k0 + r) * N + n0 + tx];
    __syncthreads();
    #pragma unroll
    for (int r = ty; r < 32; r += 8)
        Wt[(size_t)(n0 + r) * K + k0 + tx] = __float2half_rn(t[tx][r]);
}

// ----------------------------------------------------------------------------
// build_x (fp32 residual stream)
// ----------------------------------------------------------------------------
__global__ void build_x_kernel(const float* __restrict__ vm,
                               const float* __restrict__ ns,
                               const float* __restrict__ pm,
                               const float* __restrict__ pmW, const float* __restrict__ pmb,
                               const float* __restrict__ vmW, const float* __restrict__ vmb,
                               float* __restrict__ x)
{
    int idx = blockIdx.x * blockDim.x + threadIdx.x;
    if (idx >= M_ * D_) return;
    int d = idx & (D_ - 1);
    int sb = idx >> 9;
    int s = sb % S_;
    int b = sb / S_;
    float val;
    if (s == 0) {
        val = ns[b];
    } else if (s <= NPM_) {
        const float* st = pm + ((size_t)b * NPM_ + (s - 1)) * 16;
        val = pmb[d];
        #pragma unroll
        for (int c = 0; c < 16; c++) val += st[c] * pmW[c * D_ + d];
    } else if (s < S_ - 1) {
        const float* st = vm + ((size_t)b * NVM_ + (s - 1 - NPM_)) * 16;
        val = vmb[d];
        #pragma unroll
        for (int c = 0; c < 16; c++) val += st[c] * vmW[c * D_ + d];
    } else {
        val = -1.0f;
    }
    x[idx] = val;
}

// ----------------------------------------------------------------------------
// Counting sort of inner tokens by rel value (one block per batch).
// ----------------------------------------------------------------------------
__global__ void sort_kernel(const int* __restrict__ rel, int* __restrict__ sidx,
                            int* __restrict__ goff)
{
    __shared__ int hist[NPM_];
    __shared__ int offs[NPM_ + 1];
    __shared__ int relv[RELW_];
    int b = blockIdx.x, tid = threadIdx.x;
    for (int i = tid; i < NPM_; i += blockDim.x) hist[i] = 0;
    __syncthreads();
    for (int i = tid; i < RELW_; i += blockDim.x) {
        int r = rel[b * RELW_ + i];
        relv[i] = r;
        atomicAdd(&hist[r], 1);
    }
    __syncthreads();
    if (tid == 0) {
        int acc = 0;
        for (int r = 0; r < NPM_; r++) {
            offs[r] = acc;
            goff[b * (NPM_ + 1) + r] = acc;
            acc += hist[r];
        }
        goff[b * (NPM_ + 1) + NPM_] = acc;
        int* out = sidx + b * RELW_;
        for (int p = 0; p < RELW_; p++) {
            int r = relv[p];
            out[offs[r]++] = p + 1;
        }
    }
}

// ----------------------------------------------------------------------------
// LayerNorm: one warp per row of 512; output fp16 (GEMM A operand)
// ----------------------------------------------------------------------------
__global__ void ln_kernel(const float* __restrict__ x, __half* __restrict__ out,
                          const float* __restrict__ gs, const float* __restrict__ gb,
                          int M)
{
    int warp = (blockIdx.x * blockDim.x + threadIdx.x) >> 5;
    int lane = threadIdx.x & 31;
    if (warp >= M) return;
    const float* row = x + (size_t)warp * D_;
    float4 v[4];
    float sum = 0.f, sq = 0.f;
    #pragma unroll
    for (int j = 0; j < 4; j++) {
        v[j] = *reinterpret_cast<const float4*>(row + (lane + 32 * j) * 4);
        sum += v[j].x + v[j].y + v[j].z + v[j].w;
        sq  += v[j].x * v[j].x + v[j].y * v[j].y + v[j].z * v[j].z + v[j].w * v[j].w;
    }
    #pragma unroll
    for (int o = 16; o; o >>= 1) {
        sum += __shfl_xor_sync(0xffffffffu, sum, o);
        sq  += __shfl_xor_sync(0xffffffffu, sq,  o);
    }
    const float inv = 1.0f / (float)D_;
    float mean = sum * inv;
    float var  = sq * inv - mean * mean;
    float rstd = rsqrtf(var + 1e-5f);
    __half* orow = out + (size_t)warp * D_;
    #pragma unroll
    for (int j = 0; j < 4; j++) {
        int c = (lane + 32 * j) * 4;
        __half2 lo = __floats2half2_rn((v[j].x - mean) * rstd * gs[c + 0] + gb[c + 0],
                                       (v[j].y - mean) * rstd * gs[c + 1] + gb[c + 1]);
        __half2 hi = __floats2half2_rn((v[j].z - mean) * rstd * gs[c + 2] + gb[c + 2],
                                       (v[j].w - mean) * rstd * gs[c + 3] + gb[c + 3]);
        *reinterpret_cast<__half2*>(orow + c)     = lo;
        *reinterpret_cast<__half2*>(orow + c + 2) = hi;
    }
}

// ----------------------------------------------------------------------------
// fp16 tensor-core GEMM: C[M,N] = epi(A[M,K] @ Wt[N,K]^T + bias)
//   EPI 0: store fp32   EPI 1: fp32 C += (residual)   EPI 2: exact GELU -> fp16
// Block tile 128x128, BK=32 halfs, 128 threads (4 warps, 2x2), warp tile 64x64.
// mma.sync.m16n8k16.f32.f16.f16.f32; fp32 accumulation.
// Smem rows padded to 40 halfs: fragment bank = (20g+c)%32, full permutation.
// ----------------------------------------------------------------------------
#define MMA_F16(d, a, b)                                                         \
    asm volatile(                                                                \
        "mma.sync.aligned.m16n8k16.row.col.f32.f16.f16.f32 "                     \
        "{%0,%1,%2,%3}, {%4,%5,%6,%7}, {%8,%9}, {%0,%1,%2,%3};"                  \
        : "+f"((d)[0]), "+f"((d)[1]), "+f"((d)[2]), "+f"((d)[3])                 \
        : "r"((a)[0]), "r"((a)[1]), "r"((a)[2]), "r"((a)[3]),                    \
          "r"((b)[0]), "r"((b)[1]))

template<int EPI>
__global__ void __launch_bounds__(128) hgemm_kernel(
    const __half* __restrict__ A, const __half* __restrict__ Wt,
    const float* __restrict__ bias, void* __restrict__ Cv,
    int M, int N, int K)
{
    __shared__ __half As[2][128][40];
    __shared__ __half Bs[2][128][40];

    const int tid  = threadIdx.x;
    const int lane = tid & 31;
    const int wid  = tid >> 5;
    const int wm   = wid >> 1;
    const int wn   = wid & 1;
    const int g    = lane >> 2;
    const int c    = lane & 3;
    const int row0 = blockIdx.y * 128;
    const int col0 = blockIdx.x * 128;
    const int nk   = K >> 5;

    float acc[4][8][4];
    #pragma unroll
    for (int i = 0; i < 4; i++)
        #pragma unroll
        for (int j = 0; j < 8; j++)
            #pragma unroll
            for (int t = 0; t < 4; t++) acc[i][j][t] = 0.f;

    auto issue = [&](int kt, int buf) {
        const int k0 = kt << 5;
        #pragma unroll
        for (int i = 0; i < 4; i++) {
            int idx = tid + i * 128;           // 0..511
            int r = idx >> 2, q = idx & 3;     // row, 16B chunk (8 halfs)
            int m = row0 + r;
            const __half* src = A + (size_t)(m < M ? m : M - 1) * K + k0 + q * 8;
            uint32_t dst = (uint32_t)__cvta_generic_to_shared(&As[buf][r][q * 8]);
            int sz = (m < M) ? 16 : 0;
            asm volatile("cp.async.ca.shared.global [%0], [%1], 16, %2;"
                         :: "r"(dst), "l"(src), "r"(sz));
        }
        #pragma unroll
        for (int i = 0; i < 4; i++) {
            int idx = tid + i * 128;
            int r = idx >> 2, q = idx & 3;
            const __half* src = Wt + (size_t)(col0 + r) * K + k0 + q * 8;
            uint32_t dst = (uint32_t)__cvta_generic_to_shared(&Bs[buf][r][q * 8]);
            asm volatile("cp.async.ca.shared.global [%0], [%1], 16;"
                         :: "r"(dst), "l"(src));
        }
        asm volatile("cp.async.commit_group;");
    };

    issue(0, 0);

    for (int kt = 0; kt < nk; kt++) {
        const int buf = kt & 1;
        asm volatile("cp.async.wait_group 0;");
        __syncthreads();
        if (kt + 1 < nk) issue(kt + 1, (kt + 1) & 1);

        #pragma unroll
        for (int ks = 0; ks < 2; ks++) {
            const int w0 = ks * 16 + c * 2;        // half index of word (k = 2c)
            const int w4 = w0 + 8;                 // k = 2c+8
            uint32_t bf[8][2], af[4][4];
            #pragma unroll
            for (int fn = 0; fn < 8; fn++) {
                int n = wn * 64 + fn * 8 + g;
                bf[fn][0] = *reinterpret_cast<const uint32_t*>(&Bs[buf][n][w0]);
                bf[fn][1] = *reinterpret_cast<const uint32_t*>(&Bs[buf][n][w4]);
            }
            #pragma unroll
            for (int fm = 0; fm < 4; fm++) {
                int r = wm * 64 + fm * 16 + g;
                af[fm][0] = *reinterpret_cast<const uint32_t*>(&As[buf][r][w0]);
                af[fm][1] = *reinterpret_cast<const uint32_t*>(&As[buf][r + 8][w0]);
                af[fm][2] = *reinterpret_cast<const uint32_t*>(&As[buf][r][w4]);
                af[fm][3] = *reinterpret_cast<const uint32_t*>(&As[buf][r + 8][w4]);
            }
            #pragma unroll
            for (int fm = 0; fm < 4; fm++)
                #pragma unroll
                for (int fn = 0; fn < 8; fn++)
                    MMA_F16(acc[fm][fn], af[fm], bf[fn]);
        }
        __syncthreads();
    }

    // Epilogue
    const int cc = c * 2;
    #pragma unroll
    for (int fm = 0; fm < 4; fm++) {
        int mA = row0 + wm * 64 + fm * 16 + g;
        int mB = mA + 8;
        #pragma unroll
        for (int fn = 0; fn < 8; fn++) {
            int n = col0 + wn * 64 + fn * 8 + cc;
            float2 b2 = *reinterpret_cast<const float2*>(bias + n);
            float v0 = acc[fm][fn][0] + b2.x;
            float v1 = acc[fm][fn][1] + b2.y;
            float v2 = acc[fm][fn][2] + b2.x;
            float v3 = acc[fm][fn][3] + b2.y;
            if (EPI == 0) {
                float* C = (float*)Cv;
                if (mA < M) *reinterpret_cast<float2*>(C + (size_t)mA * N + n) = make_float2(v0, v1);
                if (mB < M) *reinterpret_cast<float2*>(C + (size_t)mB * N + n) = make_float2(v2, v3);
            } else if (EPI == 1) {
                float* C = (float*)Cv;
                if (mA < M) {
                    float2* p = reinterpret_cast<float2*>(C + (size_t)mA * N + n);
                    float2 o = *p; o.x += v0; o.y += v1; *p = o;
                }
                if (mB < M) {
                    float2* p = reinterpret_cast<float2*>(C + (size_t)mB * N + n);
                    float2 o = *p; o.x += v2; o.y += v3; *p = o;
                }
            } else {
                __half* C = (__half*)Cv;
                float g0 = 0.5f * v0 * (1.0f + erff(v0 * 0.70710678118654752f));
                float g1 = 0.5f * v1 * (1.0f + erff(v1 * 0.70710678118654752f));
                float g2 = 0.5f * v2 * (1.0f + erff(v2 * 0.70710678118654752f));
                float g3 = 0.5f * v3 * (1.0f + erff(v3 * 0.70710678118654752f));
                if (mA < M) *reinterpret_cast<__half2*>(C + (size_t)mA * N + n) = __floats2half2_rn(g0, g1);
                if (mB < M) *reinterpret_cast<__half2*>(C + (size_t)mB * N + n) = __floats2half2_rn(g2, g3);
            }
        }
    }
}

// ----------------------------------------------------------------------------
// Sparse group attention: one warp per (b, h, inner query). fp32 math, fp16 out.
// ----------------------------------------------------------------------------
__global__ void grp_attn_kernel(const float* __restrict__ qkv,
                                const int* __restrict__ rel,
                                const int* __restrict__ sidx,
                                const int* __restrict__ goff,
                                const unsigned char* __restrict__ padm,
                                __half* __restrict__ obuf)
{
    int gw = (blockIdx.x * blockDim.x + threadIdx.x) >> 5;
    int lane = threadIdx.x & 31;
    if (gw >= B_ * H_ * RELW_) return;
    int qi = gw % RELW_;
    int bh = gw / RELW_;
    int h = bh % H_, b = bh / H_;
    int qpos = 1 + qi;

    const size_t rs = 3 * D_;
    const float* base = qkv + (size_t)b * S_ * rs + h * DH_;
    const float* qrow = base + (size_t)qpos * rs;
    float q0 = qrow[lane], q1 = qrow[lane + 32];

    int r   = rel[b * RELW_ + qi];
    int beg = goff[b * (NPM_ + 1) + r];
    int end = goff[b * (NPM_ + 1) + r + 1];

    float m = -1e30f, l = 0.f, o0 = 0.f, o1 = 0.f;

    for (int it = -2; it < end - beg; it++) {
        int kpos;
        if (it == -2)      kpos = 0;
        else if (it == -1) kpos = S_ - 1;
        else {
            kpos = sidx[b * RELW_ + beg + it];
            if (kpos > NPM_ && padm[b * NVM_ + kpos - 1 - NPM_]) continue;
        }
        const float* krow = base + (size_t)kpos * rs + D_;
        float p = q0 * krow[lane] + q1 * krow[lane + 32];
        #pragma unroll
        for (int o = 16; o; o >>= 1) p += __shfl_xor_sync(0xffffffffu, p, o);
        float s = p * 0.125f;
        float mn = fmaxf(m, s);
        float corr = __expf(m - mn);
        float pe   = __expf(s - mn);
        const float* vrow = krow + D_;
        o0 = o0 * corr + pe * vrow[lane];
        o1 = o1 * corr + pe * vrow[lane + 32];
        l  = l * corr + pe;
        m  = mn;
    }

    float inv = 1.0f / l;
    __half* dst = obuf + ((size_t)b * S_ + qpos) * D_ + h * DH_;
    dst[lane]      = __float2half_rn(o0 * inv);
    dst[lane + 32] = __float2half_rn(o1 * inv);
}

// ----------------------------------------------------------------------------
// Dense rows: q in {0, S-1}.
// ----------------------------------------------------------------------------
__global__ void dense_attn_kernel(const float* __restrict__ qkv,
                                  const unsigned char* __restrict__ padm,
                                  __half* __restrict__ obuf)
{
    __shared__ float sm[8], sl[8], so[8][64];
    int bx = blockIdx.x;
    int qsel = bx & 1;
    int h = (bx >> 1) & (H_ - 1);
    int b = bx >> 4;
    int qpos = qsel ? (S_ - 1) : 0;
    int warp = threadIdx.x >> 5, lane = threadIdx.x & 31;

    const size_t rs = 3 * D_;
    const float* base = qkv + (size_t)b * S_ * rs + h * DH_;
    const float* qrow = base + (size_t)qpos * rs;
    float q0 = qrow[lane], q1 = qrow[lane + 32];

    float m = -1e30f, l = 0.f, o0 = 0.f, o1 = 0.f;
    for (int k = warp; k < S_; k += 8) {
        if (k > NPM_ && k < S_ - 1 && padm[b * NVM_ + k - 1 - NPM_]) continue;
        const float* krow = base + (size_t)k * rs + D_;
        float p = q0 * krow[lane] + q1 * krow[lane + 32];
        #pragma unroll
        for (int o = 16; o; o >>= 1) p += __shfl_xor_sync(0xffffffffu, p, o);
        float s = p * 0.125f;
        float mn = fmaxf(m, s);
        float corr = __expf(m - mn);
        float pe   = __expf(s - mn);
        const float* vrow = krow + D_;
        o0 = o0 * corr + pe * vrow[lane];
        o1 = o1 * corr + pe * vrow[lane + 32];
        l  = l * corr + pe;
        m  = mn;
    }
    if (lane == 0) { sm[warp] = m; sl[warp] = l; }
    so[warp][lane]      = o0;
    so[warp][lane + 32] = o1;
    __syncthreads();

    if (threadIdx.x < 64) {
        float M = -1e30f;
        #pragma unroll
        for (int w = 0; w < 8; w++) M = fmaxf(M, sm[w]);
        float L = 0.f, ov = 0.f;
        #pragma unroll
        for (int w = 0; w < 8; w++) {
            float e = __expf(sm[w] - M);
            L  += sl[w] * e;
            ov += so[w][threadIdx.x] * e;
        }
        __half* dst = obuf + ((size_t)b * S_ + qpos) * D_ + h * DH_;
        dst[threadIdx.x] = __float2half_rn(ov / L);
    }
}

// ----------------------------------------------------------------------------
// Output heads
// ----------------------------------------------------------------------------
__global__ void out_kernel(const float* __restrict__ x,
                           const float* __restrict__ outW, const float* __restrict__ outb,
                           const float* __restrict__ crW,  const float* __restrict__ crb,
                           float* __restrict__ out)
{
    int warp = (blockIdx.x * blockDim.x + threadIdx.x) >> 5;
    int lane = threadIdx.x & 31;
    const int nscore = B_ * NVM_;
    if (warp >= nscore + B_) return;
    int b, s;
    const float* w;
    float bias;
    float* dst;
    if (warp < nscore) {
        b = warp / NVM_;
        s = 1 + NPM_ + (warp % NVM_);
        w = outW; bias = outb[0];
        dst = out + warp;
    } else {
        b = warp - nscore;
        s = S_ - 1;
        w = crW; bias = crb[0];
        dst = out + nscore + b;
    }
    const float* row = x + ((size_t)b * S_ + s) * D_;
    float sum = 0.f;
    for (int c = lane; c < D_; c += 32) sum += row[c] * w[c];
    #pragma unroll
    for (int o = 16; o; o >>= 1) sum += __shfl_xor_sync(0xffffffffu, sum, o);
    if (lane == 0) *dst = sum + bias;
}

// ----------------------------------------------------------------------------
// Host launcher
// ----------------------------------------------------------------------------
extern "C" void kernel_launch(void* const* d_in, const int* in_sizes, int n_in,
                              void* d_out, int out_size)
{
    const float* vm   = (const float*)d_in[0];
    const float* ns   = (const float*)d_in[1];
    const float* pm   = (const float*)d_in[2];
    const int*   rel  = (const int*)  d_in[3];
    const unsigned char* padm = (const unsigned char*)d_in[4];
    const float* pmW  = (const float*)d_in[5];
    const float* pmb  = (const float*)d_in[6];
    const float* vmW  = (const float*)d_in[7];
    const float* vmb  = (const float*)d_in[8];
    const float* ln1s = (const float*)d_in[9];
    const float* ln1b = (const float*)d_in[10];
    const float* Wqkv = (const float*)d_in[11];
    const float* bqkv = (const float*)d_in[12];
    const float* Wo   = (const float*)d_in[13];
    const float* bo   = (const float*)d_in[14];
    const float* ln2s = (const float*)d_in[15];
    const float* ln2b = (const float*)d_in[16];
    const float* W1   = (const float*)d_in[17];
    const float* b1   = (const float*)d_in[18];
    const float* W2   = (const float*)d_in[19];
    const float* b2   = (const float*)d_in[20];
    const float* outW = (const float*)d_in[21];
    const float* outb = (const float*)d_in[22];
    const float* crW  = (const float*)d_in[23];
    const float* crb  = (const float*)d_in[24];

    float *x, *qkvb;
    __half *h, *ob, *ff, *wqkv, *wo, *w1, *w2;
    int *sidx, *goff;
    cudaGetSymbolAddress((void**)&x,    g_x);
    cudaGetSymbolAddress((void**)&h,    g_h);
    cudaGetSymbolAddress((void**)&qkvb, g_qkv);
    cudaGetSymbolAddress((void**)&ob,   g_o);
    cudaGetSymbolAddress((void**)&ff,   g_ff);
    cudaGetSymbolAddress((void**)&wqkv, g_wqkv);
    cudaGetSymbolAddress((void**)&wo,   g_wo);
    cudaGetSymbolAddress((void**)&w1,   g_w1);
    cudaGetSymbolAddress((void**)&w2,   g_w2);
    cudaGetSymbolAddress((void**)&sidx, g_sidx);
    cudaGetSymbolAddress((void**)&goff, g_goff);

    // transpose + fp16 weights once per launch: [K,N] -> [N,K]
    {
        dim3 tb(32, 8);
        for (int i = 0; i < NL_; i++) {
            transpose_h_kernel<<<dim3(3 * D_ / 32, D_ / 32), tb>>>(
                Wqkv + (size_t)i * D_ * 3 * D_, wqkv + (size_t)i * D_ * 3 * D_, D_, 3 * D_);
            transpose_h_kernel<<<dim3(D_ / 32, D_ / 32), tb>>>(
                Wo + (size_t)i * D_ * D_, wo + (size_t)i * D_ * D_, D_, D_);
            transpose_h_kernel<<<dim3(DFF_ / 32, D_ / 32), tb>>>(
                W1 + (size_t)i * D_ * DFF_, w1 + (size_t)i * D_ * DFF_, D_, DFF_);
            transpose_h_kernel<<<dim3(D_ / 32, DFF_ / 32), tb>>>(
                W2 + (size_t)i * DFF_ * D_, w2 + (size_t)i * DFF_ * D_, DFF_, D_);
        }
    }

    // group structure
    sort_kernel<<<B_, 256>>>(rel, sidx, goff);

    // build x
    {
        int total = M_ * D_;
        build_x_kernel<<<(total + 255) / 256, 256>>>(vm, ns, pm, pmW, pmb, vmW, vmb, x);
    }

    const int lnBlocks = (M_ * 32 + 255) / 256;
    const int MB = (M_ + 127) / 128;               // 54
    const dim3 gQKV(3 * D_ / 128, MB);             // (12, 54)
    const dim3 gWO (D_ / 128,     MB);             // (4, 54)
    const dim3 gW1 (DFF_ / 128,   MB);             // (16, 54)
    const dim3 gW2 (D_ / 128,     MB);             // (4, 54)
    const int grpBlocks = (B_ * H_ * RELW_) / 8;   // 6800
    const int denseBlocks = B_ * H_ * 2;           // 64

    for (int i = 0; i < NL_; i++) {
        ln_kernel<<<lnBlocks, 256>>>(x, h, ln1s + i * D_, ln1b + i * D_, M_);
        hgemm_kernel<0><<<gQKV, 128>>>(h, wqkv + (size_t)i * D_ * 3 * D_,
                                       bqkv + i * 3 * D_, qkvb, M_, 3 * D_, D_);
        grp_attn_kernel<<<grpBlocks, 256>>>(qkvb, rel, sidx, goff, padm, ob);
        dense_attn_kernel<<<denseBlocks, 256>>>(qkvb, padm, ob);
        hgemm_kernel<1><<<gWO, 128>>>(ob, wo + (size_t)i * D_ * D_,
                                      bo + i * D_, x, M_, D_, D_);
        ln_kernel<<<lnBlocks, 256>>>(x, h, ln2s + i * D_, ln2b + i * D_, M_);
        hgemm_kernel<2><<<gW1, 128>>>(h, w1 + (size_t)i * D_ * DFF_,
                                      b1 + i * DFF_, ff, M_, DFF_, D_);
        hgemm_kernel<1><<<gW2, 128>>>(ff, w2 + (size_t)i * DFF_ * D_,
                                      b2 + i * D_, x, M_, D_, DFF_);
    }

    {
        int warps = B_ * NVM_ + B_;
        out_kernel<<<(warps * 32 + 255) / 256, 256>>>(x, outW, outb, crW, crb, (float*)d_out);
    }
}